// round 1
// baseline (speedup 1.0000x reference)
#include <cuda_runtime.h>

// SmileMoENorm: per-token LayerNorm with top-2 expert-blended affine params.
//   probs = softmax(logits); top2; w /= sum(w)   ==>  w1 = sigmoid(l1 - l0)
//   out = (x - mean) * rsqrt(var + eps) * (w0*g[e0] + w1*g[e1]) + (w0*b[e0] + w1*b[e1])
//
// Layout: N_TOKENS=131072, HIDDEN=1024, NUM_EXPERTS=8.
// One warp per token. Each lane owns 32 floats (8 x float4, stride-32-float4
// across the row => coalesced 512B segments per iteration). Row cached in
// registers: exactly one global read + one global write per element.

#define N_TOKENS    131072
#define HIDDEN      1024
#define NUM_EXPERTS 8
#define H4          (HIDDEN / 4)      // 256 float4 per row
#define EPS         1e-5f

__global__ __launch_bounds__(256, 4)
void smile_moe_norm_kernel(const float4* __restrict__ x,
                           const float4* __restrict__ logits4,   // [N, 2] float4
                           const float4* __restrict__ gamma,     // [E, 256]
                           const float4* __restrict__ beta,      // [E, 256]
                           float4* __restrict__ out) {
    const int warp_in_block = threadIdx.x >> 5;
    const int lane          = threadIdx.x & 31;
    const int token         = blockIdx.x * (blockDim.x >> 5) + warp_in_block;
    if (token >= N_TOKENS) return;

    // ---- router: top-2 of 8 logits, renormalized softmax weights ----------
    // Every lane computes redundantly (2 broadcast float4 loads; L1 served).
    const float4 la = logits4[token * 2 + 0];
    const float4 lb = logits4[token * 2 + 1];
    float l[NUM_EXPERTS] = { la.x, la.y, la.z, la.w, lb.x, lb.y, lb.z, lb.w };

    float best = l[0], second = -3.4e38f;
    int   e0 = 0,     e1 = 0;
    #pragma unroll
    for (int i = 1; i < NUM_EXPERTS; i++) {
        float v = l[i];
        if (v > best)        { second = best; e1 = e0; best = v; e0 = i; }
        else if (v > second) { second = v; e1 = i; }
    }
    // renormalized top-2 softmax: full-softmax denominator cancels
    const float t  = __expf(second - best);     // <= 1, no overflow
    const float w0 = 1.0f / (1.0f + t);
    const float w1 = 1.0f - w0;

    // ---- pass over row: load into registers, accumulate sum / sumsq -------
    const float4* xr = x + (size_t)token * H4;
    float4 v[8];
    float sum = 0.0f, sq = 0.0f;
    #pragma unroll
    for (int k = 0; k < 8; k++) {
        v[k] = xr[lane + 32 * k];
        sum += v[k].x + v[k].y + v[k].z + v[k].w;
        sq  += v[k].x * v[k].x + v[k].y * v[k].y
             + v[k].z * v[k].z + v[k].w * v[k].w;
    }
    #pragma unroll
    for (int off = 16; off > 0; off >>= 1) {
        sum += __shfl_xor_sync(0xFFFFFFFFu, sum, off);
        sq  += __shfl_xor_sync(0xFFFFFFFFu, sq,  off);
    }
    const float mean = sum * (1.0f / HIDDEN);
    const float var  = sq * (1.0f / HIDDEN) - mean * mean;
    const float rstd = rsqrtf(var + EPS);

    // ---- normalize + blended affine + store -------------------------------
    const float4* g0 = gamma + e0 * H4;
    const float4* g1 = gamma + e1 * H4;
    const float4* b0 = beta  + e0 * H4;
    const float4* b1 = beta  + e1 * H4;
    float4* orow = out + (size_t)token * H4;

    #pragma unroll
    for (int k = 0; k < 8; k++) {
        const int h = lane + 32 * k;
        const float4 ga = g0[h], gb = g1[h];
        const float4 ba = b0[h], bb = b1[h];
        float4 o;
        o.x = (v[k].x - mean) * rstd * (w0 * ga.x + w1 * gb.x) + (w0 * ba.x + w1 * bb.x);
        o.y = (v[k].y - mean) * rstd * (w0 * ga.y + w1 * gb.y) + (w0 * ba.y + w1 * bb.y);
        o.z = (v[k].z - mean) * rstd * (w0 * ga.z + w1 * gb.z) + (w0 * ba.z + w1 * bb.z);
        o.w = (v[k].w - mean) * rstd * (w0 * ga.w + w1 * gb.w) + (w0 * ba.w + w1 * bb.w);
        orow[h] = o;
    }
}

extern "C" void kernel_launch(void* const* d_in, const int* in_sizes, int n_in,
                              void* d_out, int out_size) {
    const float4* x       = (const float4*)d_in[0];  // hidden_states [N, H]
    const float4* logits4 = (const float4*)d_in[1];  // router_logits [N, 8]
    const float4* gamma   = (const float4*)d_in[2];  // [E, H]
    const float4* beta    = (const float4*)d_in[3];  // [E, H]
    float4* out           = (float4*)d_out;

    const int warps_per_block = 8;                   // 256 threads
    const int blocks = N_TOKENS / warps_per_block;   // 16384
    smile_moe_norm_kernel<<<blocks, warps_per_block * 32>>>(
        x, logits4, gamma, beta, out);
}